// round 16
// baseline (speedup 1.0000x reference)
#include <cuda_runtime.h>

// ARXCell, B = 16384 rows:
//   a2[b]       = dot(iw, itdl[b,0:2048]) + dot(ow, otdl[b,0:64]) + bias
//   itdl_new[b] = [ itdl[b,64:2048], input[b,0:64] ]
//   otdl_new[b] = [ otdl[b,1:64], a2[b] ]
//   outputs[b]  = a2[b]
//
// Output layout: [ outputs(16384) | itdl_new(16384*2048) | otdl_new(16384*64) ]
//
// TWO ROWS PER WARP, fully unrolled (no loop back-edge): rows 2b and 2b+1
// share the iw weight loads (halves L1 weight traffic) and halve the wave
// count (1024 CTAs, occ-4 -> 1.73 waves vs 3.46). Depth-2 rolling prefetch
// per stream x 2 streams = 4 LDG.128 in flight per warp (same proven queue
// pressure as the PF=4 single-row design). itdl still read ONCE per element.

#define BATCH       16384
#define DI          2048
#define DO          64
#define NIN         64
#define DI4         (DI / 4)     // 512 float4 per row
#define SHIFT4      (NIN / 4)    // 16 float4 shift

__global__ __launch_bounds__(256, 4)
void arx_cell_kernel(const float* __restrict__ input,   // [B, 64]
                     const float* __restrict__ itdl,    // [B, 2048]
                     const float* __restrict__ otdl,    // [B, 64]
                     const float* __restrict__ iw,      // [2048]
                     const float* __restrict__ ow,      // [64]
                     const float* __restrict__ bias,    // [1]
                     float* __restrict__ out_a2,        // [B]
                     float* __restrict__ out_itdl,      // [B, 2048]
                     float* __restrict__ out_otdl)      // [B, 64]
{
    const int gtid = blockIdx.x * blockDim.x + threadIdx.x;
    const int wrp  = gtid >> 5;          // warp id -> row pair
    const int lane = gtid & 31;
    const int r0   = wrp * 2;            // rows r0, r0+1
    if (r0 >= BATCH) return;

    const float4* __restrict__ iw4 = reinterpret_cast<const float4*>(iw);
    const float4* __restrict__ ita = reinterpret_cast<const float4*>(itdl) + (size_t)r0 * DI4;
    const float4* __restrict__ itb = ita + DI4;
    float4* __restrict__ nita = reinterpret_cast<float4*>(out_itdl) + (size_t)r0 * DI4;
    float4* __restrict__ nitb = nita + DI4;

    // Small streams early: latency overlaps the main loop.
    const float2* __restrict__ in2 = reinterpret_cast<const float2*>(input) + (size_t)r0 * (NIN / 2);
    const float2* __restrict__ ot2 = reinterpret_cast<const float2*>(otdl)  + (size_t)r0 * (DO  / 2);
    const float2 iva = __ldcs(in2 + lane);
    const float2 ivb = __ldcs(in2 + (NIN / 2) + lane);
    const float2 ova = __ldcs(ot2 + lane);
    const float2 ovb = __ldcs(ot2 + (DO / 2) + lane);

    float acca = 0.0f, accb = 0.0f;

    // Depth-2 rolling prefetch per stream (4 LDG.128 in flight per warp).
    float4 xa[2], xb[2];
    #pragma unroll
    for (int j = 0; j < 2; ++j) {
        xa[j] = __ldcs(ita + j * 32 + lane);
        xb[j] = __ldcs(itb + j * 32 + lane);
    }

    #pragma unroll
    for (int j = 0; j < 16; ++j) {
        const float4 ca = xa[j & 1];
        const float4 cb = xb[j & 1];
        if (j + 2 < 16) {
            xa[j & 1] = __ldcs(ita + (j + 2) * 32 + lane);
            xb[j & 1] = __ldcs(itb + (j + 2) * 32 + lane);
        }

        const int v = j * 32 + lane;
        const float4 w = iw4[v];             // ONE weight load feeds BOTH rows
        acca = fmaf(ca.x, w.x, acca);
        accb = fmaf(cb.x, w.x, accb);
        acca = fmaf(ca.y, w.y, acca);
        accb = fmaf(cb.y, w.y, accb);
        acca = fmaf(ca.z, w.z, acca);
        accb = fmaf(cb.z, w.z, accb);
        acca = fmaf(ca.w, w.w, acca);
        accb = fmaf(cb.w, w.w, accb);
        if (v >= SHIFT4) {
            __stcs(nita + (v - SHIFT4), ca);
            __stcs(nitb + (v - SHIFT4), cb);
        }
    }

    // Append input at itdl_new[r, 1984:2048] (float2-aligned).
    {
        float2* __restrict__ da = reinterpret_cast<float2*>(out_itdl + (size_t)r0 * DI + (DI - NIN));
        float2* __restrict__ db = reinterpret_cast<float2*>(out_itdl + (size_t)(r0 + 1) * DI + (DI - NIN));
        __stcs(da + lane, iva);
        __stcs(db + lane, ivb);
    }

    // otdl dot contributions.
    {
        const float2 w2 = reinterpret_cast<const float2*>(ow)[lane];
        acca = fmaf(ova.x, w2.x, acca);
        accb = fmaf(ovb.x, w2.x, accb);
        acca = fmaf(ova.y, w2.y, acca);
        accb = fmaf(ovb.y, w2.y, accb);
    }

    // Warp butterfly reduction on both accumulators.
    #pragma unroll
    for (int off = 16; off > 0; off >>= 1) {
        acca += __shfl_xor_sync(0xffffffffu, acca, off);
        accb += __shfl_xor_sync(0xffffffffu, accb, off);
    }
    const float bb  = bias[0];
    const float a2a = acca + bb;
    const float a2b = accb + bb;

    // otdl shift-by-1, fully coalesced float2 per lane; slot 63 = a2.
    {
        const float nxta = __shfl_down_sync(0xffffffffu, ova.x, 1);
        const float nxtb = __shfl_down_sync(0xffffffffu, ovb.x, 1);
        float2 oa, ob;
        oa.x = ova.y;  oa.y = (lane == 31) ? a2a : nxta;
        ob.x = ovb.y;  ob.y = (lane == 31) ? a2b : nxtb;
        float2* __restrict__ noa = reinterpret_cast<float2*>(out_otdl + (size_t)r0 * DO);
        __stcs(noa + lane, oa);
        __stcs(noa + (DO / 2) + lane, ob);
    }

    if (lane == 0) {
        out_a2[r0]     = a2a;
        out_a2[r0 + 1] = a2b;
    }
}

extern "C" void kernel_launch(void* const* d_in, const int* in_sizes, int n_in,
                              void* d_out, int out_size) {
    const float* input = (const float*)d_in[0];
    const float* itdl  = (const float*)d_in[1];
    const float* otdl  = (const float*)d_in[2];
    const float* iw    = (const float*)d_in[3];
    const float* ow    = (const float*)d_in[4];
    const float* bias  = (const float*)d_in[5];

    float* out      = (float*)d_out;
    float* out_a2   = out;
    float* out_itdl = out + BATCH;
    float* out_otdl = out + BATCH + (size_t)BATCH * DI;

    const int threads = 256;                          // 8 warps -> 16 rows/CTA
    const int blocks  = BATCH / (2 * (threads / 32)); // 1024

    arx_cell_kernel<<<blocks, threads>>>(input, itdl, otdl, iw, ow, bias,
                                         out_a2, out_itdl, out_otdl);
}